// round 4
// baseline (speedup 1.0000x reference)
#include <cuda_runtime.h>
#include <cstdint>
#include <math.h>

// Problem constants (fixed shapes from reference)
#define TOKENS 32768   // B*S = 8*4096
#define EDIM   512
#define FFN    2048
#define NQ     8

// Tiling
#define BM 128
#define BN 256
#define BK 32
#define KPAD 36        // smem row stride (floats) for hs/ws -> conflict-free frag loads
#define QPAD 12        // qv row stride (floats), 16B-aligned rows
#define THREADS 512

#define SMEM_BYTES ((BN * KPAD + BM * KPAD + BM * QPAD) * 4)

// round-to-nearest tf32 (zero-mean rounding error; truncation would bias ~2^-11)
__device__ __forceinline__ unsigned f2tf(float f) {
    unsigned r;
    asm("cvt.rna.tf32.f32 %0, %1;" : "=r"(r) : "f"(f));
    return r;
}

__device__ __forceinline__ void mma_tf32(float* d, const unsigned* a, unsigned b0, unsigned b1) {
    asm volatile(
        "mma.sync.aligned.m16n8k8.row.col.f32.tf32.tf32.f32 "
        "{%0,%1,%2,%3}, {%4,%5,%6,%7}, {%8,%9}, {%0,%1,%2,%3};"
        : "+f"(d[0]), "+f"(d[1]), "+f"(d[2]), "+f"(d[3])
        : "r"(a[0]), "r"(a[1]), "r"(a[2]), "r"(a[3]), "r"(b0), "r"(b1));
}

__global__ void __launch_bounds__(THREADS, 1)
ffq_fused_kernel(const float* __restrict__ x,
                 const float* __restrict__ theta,
                 const float* __restrict__ W1,
                 const float* __restrict__ b1,
                 const float* __restrict__ W2,
                 const float* __restrict__ b2,
                 float* __restrict__ out)
{
    extern __shared__ unsigned char smem_raw[];
    unsigned* ws = reinterpret_cast<unsigned*>(smem_raw);       // [BN][KPAD] tf32 bits of W2 chunk
    unsigned* hs = ws + BN * KPAD;                              // [BM][KPAD] tf32 bits of h chunk
    float*    qv = reinterpret_cast<float*>(hs + BM * KPAD);    // [BM][QPAD] fp32 q-values

    const int tid  = threadIdx.x;
    const int warp = tid >> 5;
    const int lane = tid & 31;
    const int g  = lane >> 2;   // groupID (row within frag)
    const int tg = lane & 3;    // thread-in-group (col within frag)

    const int m0 = blockIdx.x * BM;   // token base
    const int n0 = blockIdx.y * BN;   // out-col base

    // warp tile placement: 4 (M) x 4 (N) warps, each 32x64
    const int wm = (warp >> 2) * 32;
    const int wn = (warp & 3) * 64;

    // ---- stage qv: q[m][k] = cos(x[token, k]) * cos(theta[k]) ----
    for (int i = tid; i < BM * NQ; i += THREADS) {
        int m = i >> 3;
        int q = i & 7;
        float xv = x[(size_t)(m0 + m) * EDIM + q];
        qv[m * QPAD + q] = cosf(xv) * cosf(theta[q]);
    }

    // accumulators: 2 m-tiles x 8 n-tiles x 4 regs
    float acc[2][8][4];
    #pragma unroll
    for (int mi = 0; mi < 2; mi++)
        #pragma unroll
        for (int ni = 0; ni < 8; ni++)
            #pragma unroll
            for (int r = 0; r < 4; r++)
                acc[mi][ni][r] = 0.0f;

    // ---- prefetch first W2 chunk into registers (4 float4 / thread) ----
    float4 pre[4];
    #pragma unroll
    for (int i = 0; i < 4; i++) {
        int idx = tid + i * THREADS;            // 0..2047
        int row = idx >> 3;                     // 0..255 (n within tile)
        int c4  = idx & 7;                      // float4 index within BK=32
        pre[i] = *reinterpret_cast<const float4*>(W2 + (size_t)(n0 + row) * FFN + c4 * 4);
    }

    const int mgrp = warp * 8;   // this warp's 8 token-rows for the h stage

    for (int kc = 0; kc < FFN; kc += BK) {
        __syncthreads();   // previous MMA stage done reading smem (covers qv on iter 0)

        // ---- store W2 chunk (rna -> tf32) ----
        #pragma unroll
        for (int i = 0; i < 4; i++) {
            int idx = tid + i * THREADS;
            int row = idx >> 3;
            int c4  = idx & 7;
            unsigned* wp = &ws[row * KPAD + c4 * 4];
            wp[0] = f2tf(pre[i].x);
            wp[1] = f2tf(pre[i].y);
            wp[2] = f2tf(pre[i].z);
            wp[3] = f2tf(pre[i].w);
        }

        // ---- compute h chunk: h[m][kk] = relu(b1[f] + sum_q qv[m][q]*W1[f][q]) ----
        {
            int f = kc + lane;   // each warp covers all 32 kk for its 8 rows
            const float4* w1p = reinterpret_cast<const float4*>(W1 + (size_t)f * NQ);
            float4 wA = w1p[0];
            float4 wB = w1p[1];
            float  bb = b1[f];
            #pragma unroll
            for (int j = 0; j < 8; j++) {
                int m = mgrp + j;
                const float4* qp = reinterpret_cast<const float4*>(&qv[m * QPAD]);
                float4 qA = qp[0];   // warp-uniform address -> broadcast
                float4 qB = qp[1];
                float s = bb;
                s += qA.x * wA.x; s += qA.y * wA.y; s += qA.z * wA.z; s += qA.w * wA.w;
                s += qB.x * wB.x; s += qB.y * wB.y; s += qB.z * wB.z; s += qB.w * wB.w;
                hs[m * KPAD + lane] = f2tf(fmaxf(s, 0.0f));
            }
        }

        __syncthreads();

        // ---- prefetch next W2 chunk (LDG in flight under the MMA stage) ----
        int kn = kc + BK;
        if (kn < FFN) {
            #pragma unroll
            for (int i = 0; i < 4; i++) {
                int idx = tid + i * THREADS;
                int row = idx >> 3;
                int c4  = idx & 7;
                pre[i] = *reinterpret_cast<const float4*>(W2 + (size_t)(n0 + row) * FFN + kn + c4 * 4);
            }
        }

        // ---- MMA stage: warp tile 32x64, 4 k-steps of 8 ----
        #pragma unroll
        for (int ks = 0; ks < 4; ks++) {
            int k = ks * 8;
            unsigned af[2][4];
            #pragma unroll
            for (int mi = 0; mi < 2; mi++) {
                int r = wm + mi * 16;
                af[mi][0] = hs[(r + g)     * KPAD + k + tg];
                af[mi][1] = hs[(r + g + 8) * KPAD + k + tg];
                af[mi][2] = hs[(r + g)     * KPAD + k + tg + 4];
                af[mi][3] = hs[(r + g + 8) * KPAD + k + tg + 4];
            }
            #pragma unroll
            for (int ni = 0; ni < 8; ni++) {
                int c = wn + ni * 8 + g;
                unsigned bf0 = ws[c * KPAD + k + tg];
                unsigned bf1 = ws[c * KPAD + k + tg + 4];
                mma_tf32(acc[0][ni], af[0], bf0, bf1);
                mma_tf32(acc[1][ni], af[1], bf0, bf1);
            }
        }
    }

    // ---- epilogue: out = acc + b2 ----
    #pragma unroll
    for (int mi = 0; mi < 2; mi++) {
        #pragma unroll
        for (int ni = 0; ni < 8; ni++) {
            int row = m0 + wm + mi * 16 + g;
            int col = n0 + wn + ni * 8 + 2 * tg;
            float b2a = b2[col];
            float b2b = b2[col + 1];
            float2 v0 = make_float2(acc[mi][ni][0] + b2a, acc[mi][ni][1] + b2b);
            float2 v1 = make_float2(acc[mi][ni][2] + b2a, acc[mi][ni][3] + b2b);
            *reinterpret_cast<float2*>(out + (size_t)row * EDIM + col)       = v0;
            *reinterpret_cast<float2*>(out + (size_t)(row + 8) * EDIM + col) = v1;
        }
    }
}

extern "C" void kernel_launch(void* const* d_in, const int* in_sizes, int n_in,
                              void* d_out, int out_size) {
    const float* x     = (const float*)d_in[0];
    const float* theta = (const float*)d_in[1];
    const float* W1    = (const float*)d_in[2];
    const float* b1    = (const float*)d_in[3];
    const float* W2    = (const float*)d_in[4];
    const float* b2    = (const float*)d_in[5];
    float* out = (float*)d_out;

    cudaFuncSetAttribute(ffq_fused_kernel,
                         cudaFuncAttributeMaxDynamicSharedMemorySize, SMEM_BYTES);

    dim3 grid(TOKENS / BM, EDIM / BN);   // (256, 2)
    ffq_fused_kernel<<<grid, THREADS, SMEM_BYTES>>>(x, theta, W1, b1, W2, b2, out);
}

// round 8
// speedup vs baseline: 1.1084x; 1.1084x over previous
#include <cuda_runtime.h>
#include <cuda_fp16.h>
#include <cstdint>
#include <math.h>

#define TOKENS 32768
#define EDIM   512
#define FFN    2048
#define NQ     8

#define BM 128
#define BN 256
#define BK 64
#define THREADS 512
#define CHUNKS (FFN / BK)   // 32

// smem byte offsets
#define OFF_QV 0                    // 128*8*4 = 4096
#define OFF_A  4096                 // 2 stages * (128 rows * 128B) = 32768
#define OFF_B  36864                // 2 stages * (256 rows * 128B) = 65536
#define SMEM_TOTAL 102400

// fp16 copy of W2, produced once per launch by prep kernel
__device__ __half g_W2h[EDIM * FFN];

__global__ void __launch_bounds__(256) prep_kernel(const float* __restrict__ W2) {
    int i = (blockIdx.x * blockDim.x + threadIdx.x) * 4;
    float4 v = *reinterpret_cast<const float4*>(W2 + i);
    __half2 h0 = __floats2half2_rn(v.x, v.y);
    __half2 h1 = __floats2half2_rn(v.z, v.w);
    __half2* dst = reinterpret_cast<__half2*>(g_W2h + i);
    dst[0] = h0;
    dst[1] = h1;
}

__device__ __forceinline__ uint32_t s2u(const void* p) {
    uint32_t a;
    asm("{ .reg .u64 t; cvta.to.shared.u64 t, %1; cvt.u32.u64 %0, t; }" : "=r"(a) : "l"(p));
    return a;
}

#define LDSM_X4(r, addr) \
    asm volatile("ldmatrix.sync.aligned.m8n8.x4.shared.b16 {%0,%1,%2,%3}, [%4];" \
        : "=r"((r)[0]), "=r"((r)[1]), "=r"((r)[2]), "=r"((r)[3]) : "r"(addr))

__device__ __forceinline__ void mma_f16(float* d, const uint32_t* a, uint32_t b0, uint32_t b1) {
    asm volatile(
        "mma.sync.aligned.m16n8k16.row.col.f32.f16.f16.f32 "
        "{%0,%1,%2,%3}, {%4,%5,%6,%7}, {%8,%9}, {%0,%1,%2,%3};"
        : "+f"(d[0]), "+f"(d[1]), "+f"(d[2]), "+f"(d[3])
        : "r"(a[0]), "r"(a[1]), "r"(a[2]), "r"(a[3]), "r"(b0), "r"(b1));
}

__global__ void __launch_bounds__(THREADS, 1)
ffq_hmma_kernel(const float* __restrict__ x, const float* __restrict__ theta,
                const float* __restrict__ W1, const float* __restrict__ b1,
                const float* __restrict__ b2, float* __restrict__ out)
{
    extern __shared__ unsigned char smem[];
    const uint32_t sb = s2u(smem);
    const int tid  = threadIdx.x;
    const int warp = tid >> 5;
    const int lane = tid & 31;
    const int g  = lane >> 2;
    const int tg = lane & 3;

    const int m0 = blockIdx.x * BM;
    const int n0 = blockIdx.y * BN;

    // warp tile: 4(M) x 4(N) warps, each 32 x 64
    const int wm = (warp >> 2) * 32;
    const int wn = (warp & 3) * 64;
    const int mgrp = warp * 8;       // h-stage rows for this warp

    // ---- stage qv: q[m][k] = cos(x[token,k]) * cos(theta[k]) ----
    float* qv = reinterpret_cast<float*>(smem + OFF_QV);
    for (int i = tid; i < BM * NQ; i += THREADS) {
        int m = i >> 3, q = i & 7;
        qv[m * 8 + q] = cosf(x[(size_t)(m0 + m) * EDIM + q]) * cosf(theta[q]);
    }
    __syncthreads();

    float acc[2][8][4];
    #pragma unroll
    for (int mi = 0; mi < 2; mi++)
        #pragma unroll
        for (int ni = 0; ni < 8; ni++)
            #pragma unroll
            for (int r = 0; r < 4; r++)
                acc[mi][ni][r] = 0.0f;

    // per-lane ldmatrix address components
    const int ar  = (lane & 7) + ((lane >> 3) & 1) * 8;   // A row within 16
    const int ac8 = ((lane >> 4) & 1) * 8;                // A col +8 (k-half)
    const int br  = (lane & 7) + ((lane >> 4) & 1) * 8;   // B row (n) within 16
    const int bc8 = ((lane >> 3) & 1) * 8;                // B col +8 (k-half)

    // ======== producer: h tile + W2 tile for chunk c into stage ds ========
    auto produce = [&](int c, int ds) {
        const uint32_t aB = sb + OFF_A + ds * 16384;
        const uint32_t bB = sb + OFF_B + ds * 32768;

        // ---- h: rows mgrp..mgrp+7, k-pair (2*lane, 2*lane+1) ----
        int f0 = c * BK + 2 * lane;
        const float4* w1p = reinterpret_cast<const float4*>(W1 + (size_t)f0 * NQ);
        float4 wa0 = w1p[0], wa1 = w1p[1];    // W1[f0][0..7]
        float4 wb0 = w1p[2], wb1 = w1p[3];    // W1[f0+1][0..7]
        float bb0 = b1[f0], bb1 = b1[f0 + 1];
        const uint32_t colsw = 4u * lane;
        #pragma unroll
        for (int j = 0; j < 8; j++) {
            int m = mgrp + j;
            const float4* qp = reinterpret_cast<const float4*>(qv + m * 8);
            float4 qa = qp[0], qb = qp[1];    // warp-uniform broadcast
            float s0 = bb0, s1 = bb1;
            s0 += qa.x * wa0.x; s1 += qa.x * wb0.x;
            s0 += qa.y * wa0.y; s1 += qa.y * wb0.y;
            s0 += qa.z * wa0.z; s1 += qa.z * wb0.z;
            s0 += qa.w * wa0.w; s1 += qa.w * wb0.w;
            s0 += qb.x * wa1.x; s1 += qb.x * wb1.x;
            s0 += qb.y * wa1.y; s1 += qb.y * wb1.y;
            s0 += qb.z * wa1.z; s1 += qb.z * wb1.z;
            s0 += qb.w * wa1.w; s1 += qb.w * wb1.w;
            float h0 = fmaxf(s0, 0.0f), h1 = fmaxf(s1, 0.0f);
            uint32_t hp;
            asm("cvt.rn.f16x2.f32 %0, %1, %2;" : "=r"(hp) : "f"(h1), "f"(h0)); // lo = h0
            uint32_t addr = aB + (uint32_t)m * 128 + (colsw ^ ((m & 7) << 4));
            asm volatile("st.shared.b32 [%0], %1;" :: "r"(addr), "r"(hp) : "memory");
        }

        // ---- W2 chunk via cp.async (fp16 scratch, pre-converted) ----
        #pragma unroll
        for (int i = 0; i < 4; i++) {
            int idx = tid + i * THREADS;           // 2048 x 16B
            int nl = idx >> 3, kq = idx & 7;
            const __half* src = g_W2h + (size_t)(n0 + nl) * FFN + c * BK + kq * 8;
            uint32_t dst = bB + (uint32_t)nl * 128 + (((uint32_t)kq * 16) ^ ((nl & 7) << 4));
            asm volatile("cp.async.cg.shared.global [%0], [%1], 16;"
                         :: "r"(dst), "l"(src) : "memory");
        }
        asm volatile("cp.async.commit_group;" ::: "memory");
    };

    // ======== consumer: MMAs for chunk in stage st ========
    auto consume = [&](int st) {
        const uint32_t aB = sb + OFF_A + st * 16384;
        const uint32_t bB = sb + OFF_B + st * 32768;
        #pragma unroll
        for (int ks = 0; ks < 4; ks++) {
            int kb = ks * 16;
            uint32_t afr[2][4];
            #pragma unroll
            for (int mi = 0; mi < 2; mi++) {
                int r = wm + mi * 16 + ar;
                uint32_t cb = (uint32_t)(kb + ac8) * 2;
                uint32_t addr = aB + (uint32_t)r * 128 + (cb ^ ((r & 7) << 4));
                LDSM_X4(afr[mi], addr);
            }
            uint32_t bfr[4][4];
            #pragma unroll
            for (int p = 0; p < 4; p++) {
                int n = wn + p * 16 + br;
                uint32_t cb = (uint32_t)(kb + bc8) * 2;
                uint32_t addr = bB + (uint32_t)n * 128 + (cb ^ ((n & 7) << 4));
                LDSM_X4(bfr[p], addr);
            }
            #pragma unroll
            for (int ni = 0; ni < 8; ni++) {
                uint32_t b0 = bfr[ni >> 1][(ni & 1) * 2 + 0];
                uint32_t b1r = bfr[ni >> 1][(ni & 1) * 2 + 1];
                mma_f16(acc[0][ni], afr[0], b0, b1r);
                mma_f16(acc[1][ni], afr[1], b0, b1r);
            }
        }
    };

    // prologue: fill stage 0
    produce(0, 0);
    asm volatile("cp.async.wait_group 0;" ::: "memory");
    __syncthreads();

    for (int c = 0; c < CHUNKS; c++) {
        int st = c & 1;
        if (c + 1 < CHUNKS) produce(c + 1, st ^ 1);
        consume(st);
        asm volatile("cp.async.wait_group 0;" ::: "memory");
        __syncthreads();
    }

    // ---- epilogue: + b2, store ----
    #pragma unroll
    for (int mi = 0; mi < 2; mi++) {
        #pragma unroll
        for (int ni = 0; ni < 8; ni++) {
            int row = m0 + wm + mi * 16 + g;
            int col = n0 + wn + ni * 8 + 2 * tg;
            float b2a = b2[col];
            float b2b = b2[col + 1];
            float2 v0 = make_float2(acc[mi][ni][0] + b2a, acc[mi][ni][1] + b2b);
            float2 v1 = make_float2(acc[mi][ni][2] + b2a, acc[mi][ni][3] + b2b);
            *reinterpret_cast<float2*>(out + (size_t)row * EDIM + col)       = v0;
            *reinterpret_cast<float2*>(out + (size_t)(row + 8) * EDIM + col) = v1;
        }
    }
}

extern "C" void kernel_launch(void* const* d_in, const int* in_sizes, int n_in,
                              void* d_out, int out_size) {
    const float* x     = (const float*)d_in[0];
    const float* theta = (const float*)d_in[1];
    const float* W1    = (const float*)d_in[2];
    const float* b1    = (const float*)d_in[3];
    const float* W2    = (const float*)d_in[4];
    const float* b2    = (const float*)d_in[5];
    float* out = (float*)d_out;

    prep_kernel<<<(EDIM * FFN / 4) / 256, 256>>>(W2);

    cudaFuncSetAttribute(ffq_hmma_kernel,
                         cudaFuncAttributeMaxDynamicSharedMemorySize, SMEM_TOTAL);
    dim3 grid(TOKENS / BM, EDIM / BN);   // (256, 2)
    ffq_hmma_kernel<<<grid, THREADS, SMEM_TOTAL>>>(x, theta, W1, b1, b2, out);
}

// round 12
// speedup vs baseline: 2.6844x; 2.4218x over previous
#include <cuda_runtime.h>
#include <cuda_fp16.h>
#include <cstdint>
#include <math.h>

#define TOKENS 32768
#define EDIM   512
#define FFN    2048
#define NQ     8

// ---------------- scratch (device globals: allowed) ----------------
__device__ __half g_W2h[EDIM * FFN];           // 2 MB
__device__ __half g_Hh[(size_t)TOKENS * FFN];  // 128 MB

// ---------------- prep: W2 -> fp16 ----------------
__global__ void __launch_bounds__(256) prep_kernel(const float* __restrict__ W2) {
    int i = (blockIdx.x * blockDim.x + threadIdx.x) * 4;
    float4 v = *reinterpret_cast<const float4*>(W2 + i);
    __half2* dst = reinterpret_cast<__half2*>(g_W2h + i);
    dst[0] = __floats2half2_rn(v.x, v.y);
    dst[1] = __floats2half2_rn(v.z, v.w);
}

// ---------------- h kernel: h = relu(q @ W1^T + b1), fp16 out ----------------
__global__ void __launch_bounds__(256)
h_kernel(const float* __restrict__ x, const float* __restrict__ theta,
         const float* __restrict__ W1, const float* __restrict__ b1)
{
    __shared__ float qv[32][8];
    const int tid = threadIdx.x;
    const int m0  = blockIdx.x * 32;

    {
        int m = tid >> 3, q = tid & 7;
        qv[m][q] = cosf(x[(size_t)(m0 + m) * EDIM + q]) * cosf(theta[q]);
    }
    __syncthreads();

    const int f0 = tid * 8;
    float w[8][8];
    #pragma unroll
    for (int i = 0; i < 8; i++) {
        const float4* p = reinterpret_cast<const float4*>(W1 + (size_t)(f0 + i) * NQ);
        float4 a = p[0], b = p[1];
        w[i][0] = a.x; w[i][1] = a.y; w[i][2] = a.z; w[i][3] = a.w;
        w[i][4] = b.x; w[i][5] = b.y; w[i][6] = b.z; w[i][7] = b.w;
    }
    float bb[8];
    {
        const float4* p = reinterpret_cast<const float4*>(b1 + f0);
        float4 a = p[0], b = p[1];
        bb[0] = a.x; bb[1] = a.y; bb[2] = a.z; bb[3] = a.w;
        bb[4] = b.x; bb[5] = b.y; bb[6] = b.z; bb[7] = b.w;
    }

    for (int m = 0; m < 32; m++) {
        float q0 = qv[m][0], q1 = qv[m][1], q2 = qv[m][2], q3 = qv[m][3];
        float q4 = qv[m][4], q5 = qv[m][5], q6 = qv[m][6], q7 = qv[m][7];
        float acc[8];
        #pragma unroll
        for (int i = 0; i < 8; i++) {
            float s = bb[i];
            s += q0 * w[i][0]; s += q1 * w[i][1];
            s += q2 * w[i][2]; s += q3 * w[i][3];
            s += q4 * w[i][4]; s += q5 * w[i][5];
            s += q6 * w[i][6]; s += q7 * w[i][7];
            acc[i] = fmaxf(s, 0.0f);
        }
        uint32_t p[4];
        #pragma unroll
        for (int i = 0; i < 4; i++)
            asm("cvt.rn.f16x2.f32 %0, %1, %2;" : "=r"(p[i])
                : "f"(acc[2 * i + 1]), "f"(acc[2 * i]));   // lo = even index
        __half* dst = g_Hh + (size_t)(m0 + m) * FFN + f0;
        asm volatile("st.global.v4.b32 [%0], {%1,%2,%3,%4};"
                     :: "l"(dst), "r"(p[0]), "r"(p[1]), "r"(p[2]), "r"(p[3]) : "memory");
    }
}

// ---------------- GEMM: out = H @ W2^T + b2 ----------------
#define BM 128
#define BN 128
#define BK 64
#define GT 256
#define STAGES 3
#define CHUNKS (FFN / BK)   // 32
#define STAGE_BYTES 32768   // A 16KB + B 16KB
#define SMEM_TOTAL (STAGES * STAGE_BYTES)   // 96 KB

__device__ __forceinline__ uint32_t s2u(const void* p) {
    uint32_t a;
    asm("{ .reg .u64 t; cvta.to.shared.u64 t, %1; cvt.u32.u64 %0, t; }" : "=r"(a) : "l"(p));
    return a;
}
#define LDSM_X4(r, addr) \
    asm volatile("ldmatrix.sync.aligned.m8n8.x4.shared.b16 {%0,%1,%2,%3}, [%4];" \
        : "=r"((r)[0]), "=r"((r)[1]), "=r"((r)[2]), "=r"((r)[3]) : "r"(addr))

__device__ __forceinline__ void mma_f16(float* d, const uint32_t* a, uint32_t b0, uint32_t b1) {
    asm volatile(
        "mma.sync.aligned.m16n8k16.row.col.f32.f16.f16.f32 "
        "{%0,%1,%2,%3}, {%4,%5,%6,%7}, {%8,%9}, {%0,%1,%2,%3};"
        : "+f"(d[0]), "+f"(d[1]), "+f"(d[2]), "+f"(d[3])
        : "r"(a[0]), "r"(a[1]), "r"(a[2]), "r"(a[3]), "r"(b0), "r"(b1));
}

__global__ void __launch_bounds__(GT, 2)
gemm_kernel(const float* __restrict__ b2, float* __restrict__ out)
{
    extern __shared__ unsigned char smem[];
    const uint32_t sb = s2u(smem);
    const int tid  = threadIdx.x;
    const int warp = tid >> 5;
    const int lane = tid & 31;
    const int g  = lane >> 2;
    const int tg = lane & 3;

    const int m0 = blockIdx.x * BM;
    const int n0 = blockIdx.y * BN;

    // warp grid 2(M) x 4(N); warp tile 64 x 32
    const int wm = (warp >> 2) * 64;
    const int wn = (warp & 3) * 32;

    // ldmatrix lane address components (proven in round 8)
    const int ar  = (lane & 7) + ((lane >> 3) & 1) * 8;
    const int ac8 = ((lane >> 4) & 1) * 8;
    const int br  = (lane & 7) + ((lane >> 4) & 1) * 8;
    const int bc8 = ((lane >> 3) & 1) * 8;

    float acc[4][4][4];
    #pragma unroll
    for (int mi = 0; mi < 4; mi++)
        #pragma unroll
        for (int ni = 0; ni < 4; ni++)
            #pragma unroll
            for (int r = 0; r < 4; r++)
                acc[mi][ni][r] = 0.0f;

    auto produce = [&](int c, int slot) {
        const uint32_t aB = sb + slot * STAGE_BYTES;
        const uint32_t bB = aB + 16384;
        #pragma unroll
        for (int i = 0; i < 8; i++) {
            int idx = tid + i * GT;                 // 0..2047
            int row = (idx >> 3) & 127;             // 0..127
            int kq  = idx & 7;
            uint32_t off = (uint32_t)row * 128 + (((uint32_t)kq * 16) ^ ((row & 7) << 4));
            if (idx < 1024) {
                const __half* src = g_Hh + (size_t)(m0 + row) * FFN + c * BK + kq * 8;
                asm volatile("cp.async.cg.shared.global [%0], [%1], 16;"
                             :: "r"(aB + off), "l"(src) : "memory");
            } else {
                const __half* src = g_W2h + (size_t)(n0 + row) * FFN + c * BK + kq * 8;
                asm volatile("cp.async.cg.shared.global [%0], [%1], 16;"
                             :: "r"(bB + off), "l"(src) : "memory");
            }
        }
        asm volatile("cp.async.commit_group;" ::: "memory");
    };

    auto consume = [&](int slot) {
        const uint32_t aB = sb + slot * STAGE_BYTES;
        const uint32_t bB = aB + 16384;
        #pragma unroll
        for (int ks = 0; ks < 4; ks++) {
            int kb = ks * 16;
            uint32_t afr[4][4];
            #pragma unroll
            for (int mi = 0; mi < 4; mi++) {
                int r = wm + mi * 16 + ar;
                uint32_t cb = (uint32_t)(kb + ac8) * 2;
                LDSM_X4(afr[mi], aB + (uint32_t)r * 128 + (cb ^ ((r & 7) << 4)));
            }
            uint32_t bfr[2][4];
            #pragma unroll
            for (int p = 0; p < 2; p++) {
                int n = wn + p * 16 + br;
                uint32_t cb = (uint32_t)(kb + bc8) * 2;
                LDSM_X4(bfr[p], bB + (uint32_t)n * 128 + (cb ^ ((n & 7) << 4)));
            }
            #pragma unroll
            for (int ni = 0; ni < 4; ni++) {
                uint32_t b0 = bfr[ni >> 1][(ni & 1) * 2 + 0];
                uint32_t b1 = bfr[ni >> 1][(ni & 1) * 2 + 1];
                #pragma unroll
                for (int mi = 0; mi < 4; mi++)
                    mma_f16(acc[mi][ni], afr[mi], b0, b1);
            }
        }
    };

    produce(0, 0);
    produce(1, 1);

    // main loop: group c must be COMPLETE before consume(c).
    // While c+1 < CHUNKS two groups are pending -> wait_group 1 drains group c.
    // Final iteration has only group c pending -> needs wait_group 0 (R9 bug fix).
    #pragma unroll 1
    for (int c = 0; c < CHUNKS - 1; c++) {
        asm volatile("cp.async.wait_group 1;" ::: "memory");
        __syncthreads();
        consume(c % STAGES);
        if (c + 2 < CHUNKS) produce(c + 2, (c + 2) % STAGES);
    }
    asm volatile("cp.async.wait_group 0;" ::: "memory");
    __syncthreads();
    consume((CHUNKS - 1) % STAGES);

    // epilogue: + b2
    #pragma unroll
    for (int mi = 0; mi < 4; mi++) {
        #pragma unroll
        for (int ni = 0; ni < 4; ni++) {
            int row = m0 + wm + mi * 16 + g;
            int col = n0 + wn + ni * 8 + 2 * tg;
            float b2a = b2[col];
            float b2b = b2[col + 1];
            float2 v0 = make_float2(acc[mi][ni][0] + b2a, acc[mi][ni][1] + b2b);
            float2 v1 = make_float2(acc[mi][ni][2] + b2a, acc[mi][ni][3] + b2b);
            *reinterpret_cast<float2*>(out + (size_t)row * EDIM + col)       = v0;
            *reinterpret_cast<float2*>(out + (size_t)(row + 8) * EDIM + col) = v1;
        }
    }
}

extern "C" void kernel_launch(void* const* d_in, const int* in_sizes, int n_in,
                              void* d_out, int out_size) {
    const float* x     = (const float*)d_in[0];
    const float* theta = (const float*)d_in[1];
    const float* W1    = (const float*)d_in[2];
    const float* b1    = (const float*)d_in[3];
    const float* W2    = (const float*)d_in[4];
    const float* b2    = (const float*)d_in[5];
    float* out = (float*)d_out;

    prep_kernel<<<(EDIM * FFN / 4) / 256, 256>>>(W2);
    h_kernel<<<TOKENS / 32, 256>>>(x, theta, W1, b1);

    cudaFuncSetAttribute(gemm_kernel,
                         cudaFuncAttributeMaxDynamicSharedMemorySize, SMEM_TOTAL);
    dim3 grid(TOKENS / BM, EDIM / BN);   // (256, 4)
    gemm_kernel<<<grid, GT, SMEM_TOTAL>>>(b2, out);
}